// round 4
// baseline (speedup 1.0000x reference)
#include <cuda_runtime.h>
#include <cuda_bf16.h>
#include <cstdint>

#define BATCH 4
#define CTX   2048
#define NEMB  1024
#define NH    16
#define HS    64
#define DM    1024
#define FF    4096
#define MTOT  (BATCH*CTX)   // 8192

typedef __nv_bfloat16 bf16;

// ================= scratch =================
__device__ float g_q[(size_t)BATCH*NH*CTX*HS];
__device__ float g_k[(size_t)BATCH*NH*CTX*HS];
__device__ float g_v[(size_t)BATCH*NH*CTX*HS];
__device__ bf16 g_xhi[(size_t)MTOT*NEMB],  g_xlo[(size_t)MTOT*NEMB];
__device__ bf16 g_bqhi[(size_t)3*DM*NEMB], g_bqlo[(size_t)3*DM*NEMB];
__device__ bf16 g_ahi[(size_t)MTOT*DM],    g_alo[(size_t)MTOT*DM];
__device__ bf16 g_w1hi[(size_t)FF*DM],     g_w1lo[(size_t)FF*DM];
__device__ bf16 g_hhi[(size_t)MTOT*FF],    g_hlo[(size_t)MTOT*FF];
__device__ bf16 g_w2hi[(size_t)DM*FF],     g_w2lo[(size_t)DM*FF];

__device__ __forceinline__ uint32_t pack2bf(float a, float b) {
    __nv_bfloat162 p(__float2bfloat16(a), __float2bfloat16(b));
    return *reinterpret_cast<uint32_t*>(&p);
}
__device__ __forceinline__ uint32_t smem_u32(const void* p) {
    uint32_t a;
    asm("{ .reg .u64 t; cvta.to.shared.u64 t, %1; cvt.u32.u64 %0, t; }" : "=r"(a) : "l"(p));
    return a;
}
__device__ __forceinline__ void cp16(uint32_t dst, const void* src) {
    asm volatile("cp.async.cg.shared.global [%0], [%1], 16;" :: "r"(dst), "l"(src));
}
#define CP_COMMIT() asm volatile("cp.async.commit_group;" ::: "memory")
#define CP_WAIT(n)  asm volatile("cp.async.wait_group %0;" :: "n"(n) : "memory")

__device__ __forceinline__ void ldm4(uint32_t* r, uint32_t addr) {
    asm volatile("ldmatrix.sync.aligned.m8n8.x4.shared.b16 {%0,%1,%2,%3}, [%4];"
        : "=r"(r[0]), "=r"(r[1]), "=r"(r[2]), "=r"(r[3]) : "r"(addr));
}
__device__ __forceinline__ void mma_bf16(float* d, const uint32_t* a, const uint32_t* b) {
    asm volatile("mma.sync.aligned.m16n8k16.row.col.f32.bf16.bf16.f32 "
        "{%0,%1,%2,%3}, {%4,%5,%6,%7}, {%8,%9}, {%0,%1,%2,%3};"
        : "+f"(d[0]), "+f"(d[1]), "+f"(d[2]), "+f"(d[3])
        : "r"(a[0]), "r"(a[1]), "r"(a[2]), "r"(a[3]), "r"(b[0]), "r"(b[1]));
}

// ================= split / transpose kernels =================
__global__ __launch_bounds__(256) void split_x_kernel(const float* __restrict__ x,
                                                      bf16* __restrict__ hi, bf16* __restrict__ lo)
{
    size_t i = (size_t)blockIdx.x * 256 + threadIdx.x;   // float4 index
    float4 v = ((const float4*)x)[i];
    float h0 = __bfloat162float(__float2bfloat16(v.x));
    float h1 = __bfloat162float(__float2bfloat16(v.y));
    float h2 = __bfloat162float(__float2bfloat16(v.z));
    float h3 = __bfloat162float(__float2bfloat16(v.w));
    ((uint2*)hi)[i] = make_uint2(pack2bf(v.x, v.y), pack2bf(v.z, v.w));
    ((uint2*)lo)[i] = make_uint2(pack2bf(v.x - h0, v.y - h1), pack2bf(v.z - h2, v.w - h3));
}

// W [K,N] row-major -> out [N,K] bf16 hi/lo
__global__ __launch_bounds__(256) void transpose_split(const float* __restrict__ W,
                                                       bf16* __restrict__ hi, bf16* __restrict__ lo,
                                                       int K, int N)
{
    __shared__ float t[32][33];
    int n0 = blockIdx.x * 32, k0 = blockIdx.y * 32;
    int tx = threadIdx.x, ty = threadIdx.y;
#pragma unroll
    for (int i = ty; i < 32; i += 8)
        t[i][tx] = W[(size_t)(k0 + i) * N + n0 + tx];
    __syncthreads();
#pragma unroll
    for (int i = ty; i < 32; i += 8) {
        float v = t[tx][i];
        bf16 h = __float2bfloat16(v);
        size_t o = (size_t)(n0 + i) * K + k0 + tx;
        hi[o] = h;
        lo[o] = __float2bfloat16(v - __bfloat162float(h));
    }
}

// Wq/Wk/Wv [H,C,D] -> bqkv[n = sel*1024 + h*64 + d][k = c]
__global__ __launch_bounds__(256) void qkv_transpose_split(const float* __restrict__ Wq,
                                                           const float* __restrict__ Wk,
                                                           const float* __restrict__ Wv,
                                                           bf16* __restrict__ hi, bf16* __restrict__ lo)
{
    __shared__ float t[32][33];
    int sel = blockIdx.z >> 4, h = blockIdx.z & 15;
    const float* W = (sel == 0 ? Wq : sel == 1 ? Wk : Wv) + (size_t)h * NEMB * HS;
    int c0 = blockIdx.x * 32, d0 = blockIdx.y * 32;
    int tx = threadIdx.x, ty = threadIdx.y;
#pragma unroll
    for (int i = ty; i < 32; i += 8)
        t[i][tx] = W[(size_t)(c0 + i) * HS + d0 + tx];
    __syncthreads();
    int nbase = sel * DM + h * HS + d0;
#pragma unroll
    for (int i = ty; i < 32; i += 8) {
        float v = t[tx][i];
        bf16 hh = __float2bfloat16(v);
        size_t o = (size_t)(nbase + i) * NEMB + c0 + tx;
        hi[o] = hh;
        lo[o] = __float2bfloat16(v - __bfloat162float(hh));
    }
}

// ================= mma.sync split-bf16 GEMM =================
// D[m,n] = sum_k A[m,k]*B[n,k]  (B stored n-major [N][K])
// hi/lo split: AhiBhi + AhiBlo + AloBhi (lo*lo dropped, ~4e-6 rel)
// MODE 0: scatter fp32 -> g_q/g_k/g_v
// MODE 1: +bias, write split bf16 (FFN1 -> h)
// MODE 2: +bias, relu, write fp32 (FFN2 -> out)
#define ROWB    80          // padded row: 40 bf16 = 80 bytes (conflict-free ldmatrix)
#define TILE_B  (128*ROWB)  // 10240 bytes per operand tile
#define OFF_AH  0
#define OFF_AL  (TILE_B)
#define OFF_BH  (2*TILE_B)
#define OFF_BL  (3*TILE_B)
#define STAGE_B (4*TILE_B)  // 40960
#define NSTAGE  3
#define GEMM_SMEM (NSTAGE*STAGE_B)   // 122880

template <int MODE>
__global__ __launch_bounds__(256, 1)
void gemm_split(const bf16* __restrict__ Ahi, const bf16* __restrict__ Alo,
                const bf16* __restrict__ Bhi, const bf16* __restrict__ Blo,
                const float* __restrict__ bias,
                float* __restrict__ out_f, bf16* __restrict__ out_hi, bf16* __restrict__ out_lo,
                float* __restrict__ oq, float* __restrict__ ok, float* __restrict__ ov,
                int N, int K)
{
    extern __shared__ char smem[];
    uint32_t sb = smem_u32(smem);

    int tid = threadIdx.x, wid = tid >> 5, lid = tid & 31;
    int wm = wid >> 2, wn = wid & 3;          // warp tile: 64(M) x 32(N)
    int bx = blockIdx.x, by = blockIdx.y;

    const bf16* aH = Ahi + (size_t)by * 128 * K;
    const bf16* aL = Alo + (size_t)by * 128 * K;
    const bf16* bH = Bhi + (size_t)bx * 128 * K;
    const bf16* bL = Blo + (size_t)bx * 128 * K;

    // per-thread global-load geometry (2 x 16B chunks per operand per stage)
    int r0 = tid >> 2, c0 = tid & 3;          // chunk 0: row r0, 16B-chunk c0
    int r1 = (tid + 256) >> 2, c1 = (tid + 256) & 3;
    uint32_t so0 = (uint32_t)(r0 * ROWB + c0 * 16);
    uint32_t so1 = (uint32_t)(r1 * ROWB + c1 * 16);

    float acc[4][4][4];
#pragma unroll
    for (int i = 0; i < 4; i++)
#pragma unroll
        for (int j = 0; j < 4; j++)
#pragma unroll
            for (int l = 0; l < 4; l++) acc[i][j][l] = 0.f;

    int ITERS = K >> 5;

#define ISSUE(st, k0) do {                                                     \
        uint32_t _b = sb + (st) * STAGE_B;                                     \
        size_t _g0 = (size_t)r0 * K + (k0) + c0 * 8;                           \
        size_t _g1 = (size_t)r1 * K + (k0) + c1 * 8;                           \
        cp16(_b + OFF_AH + so0, aH + _g0); cp16(_b + OFF_AH + so1, aH + _g1);  \
        cp16(_b + OFF_AL + so0, aL + _g0); cp16(_b + OFF_AL + so1, aL + _g1);  \
        cp16(_b + OFF_BH + so0, bH + _g0); cp16(_b + OFF_BH + so1, bH + _g1);  \
        cp16(_b + OFF_BL + so0, bL + _g0); cp16(_b + OFF_BL + so1, bL + _g1);  \
    } while (0)

    ISSUE(0, 0);  CP_COMMIT();
    ISSUE(1, 32); CP_COMMIT();

    int g = lid >> 3, rr = lid & 7;
    // ldmatrix lane geometry
    uint32_t a_row_off = (uint32_t)(((g & 1) * 8 + rr) * ROWB + (g >> 1) * 16);
    uint32_t b_row_off = (uint32_t)(((g >> 1) * 8 + rr) * ROWB + (g & 1) * 16);

    for (int it = 0; it < ITERS; it++) {
        int pre = it + NSTAGE - 1;
        if (pre < ITERS) { ISSUE(pre % NSTAGE, pre * 32); }
        CP_COMMIT();
        CP_WAIT(NSTAGE - 2);
        __syncthreads();

        uint32_t base = sb + (it % NSTAGE) * STAGE_B;
#pragma unroll
        for (int ks = 0; ks < 2; ks++) {
            uint32_t ah[4][4], al[4][4], bh[2][4], bl[2][4];
#pragma unroll
            for (int mi = 0; mi < 4; mi++) {
                uint32_t off = (uint32_t)((wm * 64 + mi * 16) * ROWB + ks * 32) + a_row_off;
                ldm4(ah[mi], base + OFF_AH + off);
                ldm4(al[mi], base + OFF_AL + off);
            }
#pragma unroll
            for (int p = 0; p < 2; p++) {
                uint32_t off = (uint32_t)((wn * 32 + p * 16) * ROWB + ks * 32) + b_row_off;
                ldm4(bh[p], base + OFF_BH + off);
                ldm4(bl[p], base + OFF_BL + off);
            }
#pragma unroll
            for (int mi = 0; mi < 4; mi++)
#pragma unroll
                for (int ni = 0; ni < 4; ni++) {
                    int p = ni >> 1, o = (ni & 1) * 2;
                    mma_bf16(acc[mi][ni], ah[mi], &bh[p][o]);
                    mma_bf16(acc[mi][ni], ah[mi], &bl[p][o]);
                    mma_bf16(acc[mi][ni], al[mi], &bh[p][o]);
                }
        }
        __syncthreads();
    }
#undef ISSUE

    // ---------------- epilogue ----------------
    int t4 = lid >> 2, t2 = (lid & 3) * 2;
#pragma unroll
    for (int mi = 0; mi < 4; mi++) {
#pragma unroll
        for (int ni = 0; ni < 4; ni++) {
            int n = bx * 128 + wn * 32 + ni * 8 + t2;
            int m0 = by * 128 + wm * 64 + mi * 16 + t4;
            float bn0 = 0.f, bn1 = 0.f;
            if (MODE != 0) { bn0 = bias[n]; bn1 = bias[n + 1]; }
#pragma unroll
            for (int half = 0; half < 2; half++) {
                int m = m0 + half * 8;
                float v0 = acc[mi][ni][half * 2];
                float v1 = acc[mi][ni][half * 2 + 1];
                if (MODE == 0) {
                    int b = m >> 11, t = m & (CTX - 1);
                    int sel = n >> 10, hh = (n & 1023) >> 6, d0 = n & 63;
                    float* op = (sel == 0 ? oq : sel == 1 ? ok : ov)
                                + ((size_t)(b * NH + hh) * CTX + t) * HS + d0;
                    *(float2*)op = make_float2(v0, v1);
                } else if (MODE == 1) {
                    v0 += bn0; v1 += bn1;
                    float h0 = __bfloat162float(__float2bfloat16(v0));
                    float h1 = __bfloat162float(__float2bfloat16(v1));
                    size_t o = (size_t)m * N + n;
                    *(uint32_t*)(out_hi + o) = pack2bf(v0, v1);
                    *(uint32_t*)(out_lo + o) = pack2bf(v0 - h0, v1 - h1);
                } else {
                    v0 = fmaxf(v0 + bn0, 0.f);
                    v1 = fmaxf(v1 + bn1, 0.f);
                    *(float2*)(out_f + (size_t)m * N + n) = make_float2(v0, v1);
                }
            }
        }
    }
}

// ================= causal flash attention (fp32, split-bf16 epilogue) =================
#define QPAD 17
#define ATTN_SMEM (128*QPAD*16 + 2*64*64*4)

__global__ __launch_bounds__(128)
void attn_kernel()
{
    extern __shared__ float fsm[];
    float* q_s = fsm;
    float* k_s = fsm + 128 * QPAD * 4;
    float* v_s = k_s + 64 * 64;

    int tid = threadIdx.x;
    int qt = blockIdx.x, h = blockIdx.y, b = blockIdx.z;
    int q0 = qt * 128;

    const float* qg = g_q + ((size_t)(b * NH + h) * CTX + q0) * HS;
    const float* kg = g_k + (size_t)(b * NH + h) * CTX * HS;
    const float* vg = g_v + (size_t)(b * NH + h) * CTX * HS;

#pragma unroll
    for (int i = 0; i < 16; i++) {
        int lin = tid + i * 128;
        int row = lin >> 4, c4 = lin & 15;
        *(float4*)&q_s[(row * QPAD + c4) * 4] = *(const float4*)(qg + (size_t)row * HS + c4 * 4);
    }

    int row = q0 + tid;
    float m = -1e30f, l = 0.f;
    float4 acc[16];
#pragma unroll
    for (int i = 0; i < 16; i++) acc[i] = make_float4(0.f, 0.f, 0.f, 0.f);

    int nkt = (q0 + 127) / 64 + 1;
    for (int kt = 0; kt < nkt; kt++) {
        int kb = kt * 64;
        __syncthreads();
#pragma unroll
        for (int i = 0; i < 8; i++) {
            int lin = tid + i * 128;
            int r = lin >> 4, c4 = lin & 15;
            *(float4*)&k_s[r * 64 + c4 * 4] = *(const float4*)(kg + (size_t)(kb + r) * HS + c4 * 4);
            *(float4*)&v_s[r * 64 + c4 * 4] = *(const float4*)(vg + (size_t)(kb + r) * HS + c4 * 4);
        }
        __syncthreads();

        const float4* q4 = (const float4*)&q_s[tid * QPAD * 4];

        for (int jc = 0; jc < 4; jc++) {
            int kb2 = kb + jc * 16;
            if (kb2 > row) break;

            float s[16];
#pragma unroll
            for (int j = 0; j < 16; j++) s[j] = 0.f;
#pragma unroll
            for (int kk = 0; kk < 16; kk++) {
                float4 qv = q4[kk];
#pragma unroll
                for (int j = 0; j < 16; j++) {
                    float4 kv = *(const float4*)&k_s[(jc * 16 + j) * 64 + kk * 4];
                    s[j] += qv.x * kv.x + qv.y * kv.y + qv.z * kv.z + qv.w * kv.w;
                }
            }
            float mx = m;
#pragma unroll
            for (int j = 0; j < 16; j++) {
                float sv = s[j] * 0.125f;
                if (kb2 + j > row) sv = -1e30f;
                s[j] = sv;
                mx = fmaxf(mx, sv);
            }
            float corr = __expf(m - mx);
            m = mx;
            l *= corr;
#pragma unroll
            for (int i = 0; i < 16; i++) {
                acc[i].x *= corr; acc[i].y *= corr; acc[i].z *= corr; acc[i].w *= corr;
            }
#pragma unroll
            for (int j = 0; j < 16; j++) {
                float p = __expf(s[j] - m);
                l += p;
                const float4* v4 = (const float4*)&v_s[(jc * 16 + j) * 64];
#pragma unroll
                for (int i = 0; i < 16; i++) {
                    float4 vv = v4[i];
                    acc[i].x += p * vv.x; acc[i].y += p * vv.y;
                    acc[i].z += p * vv.z; acc[i].w += p * vv.w;
                }
            }
        }
    }

    float inv = 1.f / l;
    size_t obase = ((size_t)b * CTX + row) * DM + h * HS;
#pragma unroll
    for (int i = 0; i < 16; i++) {
        float v0 = acc[i].x * inv, v1 = acc[i].y * inv, v2 = acc[i].z * inv, v3 = acc[i].w * inv;
        float h0 = __bfloat162float(__float2bfloat16(v0));
        float h1 = __bfloat162float(__float2bfloat16(v1));
        float h2 = __bfloat162float(__float2bfloat16(v2));
        float h3 = __bfloat162float(__float2bfloat16(v3));
        *(uint2*)(g_ahi + obase + i * 4) = make_uint2(pack2bf(v0, v1), pack2bf(v2, v3));
        *(uint2*)(g_alo + obase + i * 4) = make_uint2(pack2bf(v0 - h0, v1 - h1), pack2bf(v2 - h2, v3 - h3));
    }
}

// ================= launch =================
extern "C" void kernel_launch(void* const* d_in, const int* in_sizes, int n_in,
                              void* d_out, int out_size)
{
    const float* x  = (const float*)d_in[0];
    const float* Wq = (const float*)d_in[1];
    const float* Wk = (const float*)d_in[2];
    const float* Wv = (const float*)d_in[3];
    const float* W1 = (const float*)d_in[4];
    const float* b1 = (const float*)d_in[5];
    const float* W2 = (const float*)d_in[6];
    const float* b2 = (const float*)d_in[7];
    float* out = (float*)d_out;

    float *qp, *kp, *vp;
    bf16 *xhi, *xlo, *bqhi, *bqlo, *ahi, *alo, *w1hi, *w1lo, *hhi, *hlo, *w2hi, *w2lo;
    cudaGetSymbolAddress((void**)&qp, g_q);
    cudaGetSymbolAddress((void**)&kp, g_k);
    cudaGetSymbolAddress((void**)&vp, g_v);
    cudaGetSymbolAddress((void**)&xhi, g_xhi);
    cudaGetSymbolAddress((void**)&xlo, g_xlo);
    cudaGetSymbolAddress((void**)&bqhi, g_bqhi);
    cudaGetSymbolAddress((void**)&bqlo, g_bqlo);
    cudaGetSymbolAddress((void**)&ahi, g_ahi);
    cudaGetSymbolAddress((void**)&alo, g_alo);
    cudaGetSymbolAddress((void**)&w1hi, g_w1hi);
    cudaGetSymbolAddress((void**)&w1lo, g_w1lo);
    cudaGetSymbolAddress((void**)&hhi, g_hhi);
    cudaGetSymbolAddress((void**)&hlo, g_hlo);
    cudaGetSymbolAddress((void**)&w2hi, g_w2hi);
    cudaGetSymbolAddress((void**)&w2lo, g_w2lo);

    cudaFuncSetAttribute(gemm_split<0>, cudaFuncAttributeMaxDynamicSharedMemorySize, GEMM_SMEM);
    cudaFuncSetAttribute(gemm_split<1>, cudaFuncAttributeMaxDynamicSharedMemorySize, GEMM_SMEM);
    cudaFuncSetAttribute(gemm_split<2>, cudaFuncAttributeMaxDynamicSharedMemorySize, GEMM_SMEM);
    cudaFuncSetAttribute(attn_kernel, cudaFuncAttributeMaxDynamicSharedMemorySize, ATTN_SMEM);

    // input conversions
    split_x_kernel<<<(size_t)MTOT * NEMB / 1024, 256>>>(x, xhi, xlo);
    qkv_transpose_split<<<dim3(NEMB / 32, HS / 32, 48), dim3(32, 8)>>>(Wq, Wk, Wv, bqhi, bqlo);
    transpose_split<<<dim3(FF / 32, DM / 32), dim3(32, 8)>>>(W1, w1hi, w1lo, DM, FF);
    transpose_split<<<dim3(DM / 32, FF / 32), dim3(32, 8)>>>(W2, w2hi, w2lo, FF, DM);

    // QKV: [8192,1024] @ [1024,3072] -> scatter to g_q/g_k/g_v
    gemm_split<0><<<dim3(3 * DM / 128, MTOT / 128), 256, GEMM_SMEM>>>(
        xhi, xlo, bqhi, bqlo, nullptr, nullptr, nullptr, nullptr, qp, kp, vp, 3 * DM, NEMB);

    // attention -> att hi/lo
    attn_kernel<<<dim3(CTX / 128, NH, BATCH), 128, ATTN_SMEM>>>();

    // FFN1: [8192,1024] @ [1024,4096] + b1 -> h hi/lo
    gemm_split<1><<<dim3(FF / 128, MTOT / 128), 256, GEMM_SMEM>>>(
        ahi, alo, w1hi, w1lo, b1, nullptr, hhi, hlo, nullptr, nullptr, nullptr, FF, DM);

    // FFN2: [8192,4096] @ [4096,1024] + b2, relu -> out
    gemm_split<2><<<dim3(DM / 128, MTOT / 128), 256, GEMM_SMEM>>>(
        hhi, hlo, w2hi, w2lo, b2, out, nullptr, nullptr, nullptr, nullptr, nullptr, DM, FF);
}

// round 5
// speedup vs baseline: 1.5500x; 1.5500x over previous
#include <cuda_runtime.h>
#include <cuda_bf16.h>
#include <cstdint>

#define BATCH 4
#define CTX   2048
#define NEMB  1024
#define NH    16
#define HS    64
#define DM    1024
#define FF    4096
#define MTOT  (BATCH*CTX)   // 8192

typedef __nv_bfloat16 bf16;

// ================= scratch =================
__device__ bf16 g_qhi[(size_t)BATCH*NH*CTX*HS], g_qlo[(size_t)BATCH*NH*CTX*HS];
__device__ bf16 g_khi[(size_t)BATCH*NH*CTX*HS], g_klo[(size_t)BATCH*NH*CTX*HS];
__device__ bf16 g_vthi[(size_t)BATCH*NH*HS*CTX], g_vtlo[(size_t)BATCH*NH*HS*CTX];
__device__ bf16 g_xhi[(size_t)MTOT*NEMB],  g_xlo[(size_t)MTOT*NEMB];
__device__ bf16 g_bqhi[(size_t)3*DM*NEMB], g_bqlo[(size_t)3*DM*NEMB];
__device__ bf16 g_ahi[(size_t)MTOT*DM],    g_alo[(size_t)MTOT*DM];
__device__ bf16 g_w1hi[(size_t)FF*DM],     g_w1lo[(size_t)FF*DM];
__device__ bf16 g_hhi[(size_t)MTOT*FF],    g_hlo[(size_t)MTOT*FF];
__device__ bf16 g_w2hi[(size_t)DM*FF],     g_w2lo[(size_t)DM*FF];

__device__ __forceinline__ uint32_t pack2bf(float a, float b) {
    __nv_bfloat162 p(__float2bfloat16(a), __float2bfloat16(b));
    return *reinterpret_cast<uint32_t*>(&p);
}
__device__ __forceinline__ uint32_t packlo2(float a, float b) {
    float ra = __bfloat162float(__float2bfloat16(a));
    float rb = __bfloat162float(__float2bfloat16(b));
    return pack2bf(a - ra, b - rb);
}
__device__ __forceinline__ uint32_t smem_u32(const void* p) {
    uint32_t a;
    asm("{ .reg .u64 t; cvta.to.shared.u64 t, %1; cvt.u32.u64 %0, t; }" : "=r"(a) : "l"(p));
    return a;
}
__device__ __forceinline__ void cp16(uint32_t dst, const void* src) {
    asm volatile("cp.async.cg.shared.global [%0], [%1], 16;" :: "r"(dst), "l"(src));
}
#define CP_COMMIT() asm volatile("cp.async.commit_group;" ::: "memory")
#define CP_WAIT(n)  asm volatile("cp.async.wait_group %0;" :: "n"(n) : "memory")

__device__ __forceinline__ void ldm4(uint32_t* r, uint32_t addr) {
    asm volatile("ldmatrix.sync.aligned.m8n8.x4.shared.b16 {%0,%1,%2,%3}, [%4];"
        : "=r"(r[0]), "=r"(r[1]), "=r"(r[2]), "=r"(r[3]) : "r"(addr));
}
__device__ __forceinline__ void mma_bf16(float* d, const uint32_t* a, const uint32_t* b) {
    asm volatile("mma.sync.aligned.m16n8k16.row.col.f32.bf16.bf16.f32 "
        "{%0,%1,%2,%3}, {%4,%5,%6,%7}, {%8,%9}, {%0,%1,%2,%3};"
        : "+f"(d[0]), "+f"(d[1]), "+f"(d[2]), "+f"(d[3])
        : "r"(a[0]), "r"(a[1]), "r"(a[2]), "r"(a[3]), "r"(b[0]), "r"(b[1]));
}

// ================= split / transpose kernels =================
__global__ __launch_bounds__(256) void split_x_kernel(const float* __restrict__ x,
                                                      bf16* __restrict__ hi, bf16* __restrict__ lo)
{
    size_t i = (size_t)blockIdx.x * 256 + threadIdx.x;
    float4 v = ((const float4*)x)[i];
    ((uint2*)hi)[i] = make_uint2(pack2bf(v.x, v.y), pack2bf(v.z, v.w));
    ((uint2*)lo)[i] = make_uint2(packlo2(v.x, v.y), packlo2(v.z, v.w));
}

// W [K,N] row-major -> out [N,K] bf16 hi/lo
__global__ __launch_bounds__(256) void transpose_split(const float* __restrict__ W,
                                                       bf16* __restrict__ hi, bf16* __restrict__ lo,
                                                       int K, int N)
{
    __shared__ float t[32][33];
    int n0 = blockIdx.x * 32, k0 = blockIdx.y * 32;
    int tx = threadIdx.x, ty = threadIdx.y;
#pragma unroll
    for (int i = ty; i < 32; i += 8)
        t[i][tx] = W[(size_t)(k0 + i) * N + n0 + tx];
    __syncthreads();
#pragma unroll
    for (int i = ty; i < 32; i += 8) {
        float v = t[tx][i];
        bf16 h = __float2bfloat16(v);
        size_t o = (size_t)(n0 + i) * K + k0 + tx;
        hi[o] = h;
        lo[o] = __float2bfloat16(v - __bfloat162float(h));
    }
}

// Wq/Wk/Wv [H,C,D] -> bqkv[n = sel*1024 + h*64 + d][k = c]
__global__ __launch_bounds__(256) void qkv_transpose_split(const float* __restrict__ Wq,
                                                           const float* __restrict__ Wk,
                                                           const float* __restrict__ Wv,
                                                           bf16* __restrict__ hi, bf16* __restrict__ lo)
{
    __shared__ float t[32][33];
    int sel = blockIdx.z >> 4, h = blockIdx.z & 15;
    const float* W = (sel == 0 ? Wq : sel == 1 ? Wk : Wv) + (size_t)h * NEMB * HS;
    int c0 = blockIdx.x * 32, d0 = blockIdx.y * 32;
    int tx = threadIdx.x, ty = threadIdx.y;
#pragma unroll
    for (int i = ty; i < 32; i += 8)
        t[i][tx] = W[(size_t)(c0 + i) * HS + d0 + tx];
    __syncthreads();
    int nbase = sel * DM + h * HS + d0;
#pragma unroll
    for (int i = ty; i < 32; i += 8) {
        float v = t[tx][i];
        bf16 hh = __float2bfloat16(v);
        size_t o = (size_t)(nbase + i) * NEMB + c0 + tx;
        hi[o] = hh;
        lo[o] = __float2bfloat16(v - __bfloat162float(hh));
    }
}

// ================= mma.sync split-bf16 GEMM =================
// MODE 0: scatter split bf16 -> q/k [B,H,T,D], vt [B,H,D,T]
// MODE 1: +bias, write split bf16 (FFN1 -> h)
// MODE 2: +bias, relu, write fp32 (FFN2 -> out)
#define ROWB    80
#define TILE_B  (128*ROWB)
#define OFF_AH  0
#define OFF_AL  (TILE_B)
#define OFF_BH  (2*TILE_B)
#define OFF_BL  (3*TILE_B)
#define STAGE_B (4*TILE_B)
#define NSTAGE  3
#define GEMM_SMEM (NSTAGE*STAGE_B)   // 122880

template <int MODE>
__global__ __launch_bounds__(256, 1)
void gemm_split(const bf16* __restrict__ Ahi, const bf16* __restrict__ Alo,
                const bf16* __restrict__ Bhi, const bf16* __restrict__ Blo,
                const float* __restrict__ bias,
                float* __restrict__ out_f, bf16* __restrict__ out_hi, bf16* __restrict__ out_lo,
                bf16* __restrict__ p0hi, bf16* __restrict__ p0lo,
                bf16* __restrict__ p1hi, bf16* __restrict__ p1lo,
                int N, int K)
{
    extern __shared__ char smem[];
    uint32_t sb = smem_u32(smem);

    int tid = threadIdx.x, wid = tid >> 5, lid = tid & 31;
    int wm = wid >> 2, wn = wid & 3;
    int bx = blockIdx.x, by = blockIdx.y;

    const bf16* aH = Ahi + (size_t)by * 128 * K;
    const bf16* aL = Alo + (size_t)by * 128 * K;
    const bf16* bH = Bhi + (size_t)bx * 128 * K;
    const bf16* bL = Blo + (size_t)bx * 128 * K;

    int r0 = tid >> 2, c0 = tid & 3;
    int r1 = (tid + 256) >> 2, c1 = (tid + 256) & 3;
    uint32_t so0 = (uint32_t)(r0 * ROWB + c0 * 16);
    uint32_t so1 = (uint32_t)(r1 * ROWB + c1 * 16);

    float acc[4][4][4];
#pragma unroll
    for (int i = 0; i < 4; i++)
#pragma unroll
        for (int j = 0; j < 4; j++)
#pragma unroll
            for (int l = 0; l < 4; l++) acc[i][j][l] = 0.f;

    int ITERS = K >> 5;

#define ISSUE(st, k0) do {                                                     \
        uint32_t _b = sb + (st) * STAGE_B;                                     \
        size_t _g0 = (size_t)r0 * K + (k0) + c0 * 8;                           \
        size_t _g1 = (size_t)r1 * K + (k0) + c1 * 8;                           \
        cp16(_b + OFF_AH + so0, aH + _g0); cp16(_b + OFF_AH + so1, aH + _g1);  \
        cp16(_b + OFF_AL + so0, aL + _g0); cp16(_b + OFF_AL + so1, aL + _g1);  \
        cp16(_b + OFF_BH + so0, bH + _g0); cp16(_b + OFF_BH + so1, bH + _g1);  \
        cp16(_b + OFF_BL + so0, bL + _g0); cp16(_b + OFF_BL + so1, bL + _g1);  \
    } while (0)

    ISSUE(0, 0);  CP_COMMIT();
    ISSUE(1, 32); CP_COMMIT();

    int g = lid >> 3, rr = lid & 7;
    uint32_t a_row_off = (uint32_t)(((g & 1) * 8 + rr) * ROWB + (g >> 1) * 16);
    uint32_t b_row_off = (uint32_t)(((g >> 1) * 8 + rr) * ROWB + (g & 1) * 16);

    for (int it = 0; it < ITERS; it++) {
        int pre = it + NSTAGE - 1;
        if (pre < ITERS) { ISSUE(pre % NSTAGE, pre * 32); }
        CP_COMMIT();
        CP_WAIT(NSTAGE - 2);
        __syncthreads();

        uint32_t base = sb + (it % NSTAGE) * STAGE_B;
#pragma unroll
        for (int ks = 0; ks < 2; ks++) {
            uint32_t ah[4][4], al[4][4], bh[2][4], bl[2][4];
#pragma unroll
            for (int mi = 0; mi < 4; mi++) {
                uint32_t off = (uint32_t)((wm * 64 + mi * 16) * ROWB + ks * 32) + a_row_off;
                ldm4(ah[mi], base + OFF_AH + off);
                ldm4(al[mi], base + OFF_AL + off);
            }
#pragma unroll
            for (int p = 0; p < 2; p++) {
                uint32_t off = (uint32_t)((wn * 32 + p * 16) * ROWB + ks * 32) + b_row_off;
                ldm4(bh[p], base + OFF_BH + off);
                ldm4(bl[p], base + OFF_BL + off);
            }
#pragma unroll
            for (int mi = 0; mi < 4; mi++)
#pragma unroll
                for (int ni = 0; ni < 4; ni++) {
                    int p = ni >> 1, o = (ni & 1) * 2;
                    mma_bf16(acc[mi][ni], ah[mi], &bh[p][o]);
                    mma_bf16(acc[mi][ni], ah[mi], &bl[p][o]);
                    mma_bf16(acc[mi][ni], al[mi], &bh[p][o]);
                }
        }
        __syncthreads();
    }
#undef ISSUE

    // ---------------- epilogue ----------------
    int t4 = lid >> 2, t2 = (lid & 3) * 2;
#pragma unroll
    for (int mi = 0; mi < 4; mi++) {
#pragma unroll
        for (int ni = 0; ni < 4; ni++) {
            int n = bx * 128 + wn * 32 + ni * 8 + t2;
            int m0 = by * 128 + wm * 64 + mi * 16 + t4;
            float bn0 = 0.f, bn1 = 0.f;
            if (MODE != 0) { bn0 = bias[n]; bn1 = bias[n + 1]; }
#pragma unroll
            for (int half = 0; half < 2; half++) {
                int m = m0 + half * 8;
                float v0 = acc[mi][ni][half * 2];
                float v1 = acc[mi][ni][half * 2 + 1];
                if (MODE == 0) {
                    int b = m >> 11, t = m & (CTX - 1);
                    int sel = n >> 10, hh = (n & 1023) >> 6, d0 = n & 63;
                    if (sel == 2) {
                        size_t o = ((size_t)(b * NH + hh) * HS + d0) * CTX + t;
                        p1hi[o] = __float2bfloat16(v0);
                        p1hi[o + CTX] = __float2bfloat16(v1);
                        float ra = __bfloat162float(__float2bfloat16(v0));
                        float rb = __bfloat162float(__float2bfloat16(v1));
                        p1lo[o] = __float2bfloat16(v0 - ra);
                        p1lo[o + CTX] = __float2bfloat16(v1 - rb);
                    } else {
                        bf16* hi = (sel == 0) ? out_hi : p0hi;
                        bf16* lo = (sel == 0) ? out_lo : p0lo;
                        size_t o = ((size_t)(b * NH + hh) * CTX + t) * HS + d0;
                        *(uint32_t*)(hi + o) = pack2bf(v0, v1);
                        *(uint32_t*)(lo + o) = packlo2(v0, v1);
                    }
                } else if (MODE == 1) {
                    v0 += bn0; v1 += bn1;
                    size_t o = (size_t)m * N + n;
                    *(uint32_t*)(out_hi + o) = pack2bf(v0, v1);
                    *(uint32_t*)(out_lo + o) = packlo2(v0, v1);
                } else {
                    v0 = fmaxf(v0 + bn0, 0.f);
                    v1 = fmaxf(v1 + bn1, 0.f);
                    *(float2*)(out_f + (size_t)m * N + n) = make_float2(v0, v1);
                }
            }
        }
    }
}

// ================= mma.sync causal flash attention =================
// 128 queries/CTA, 8 warps x 16 rows; Bc=64 key tile; double-buffered K/VT.
#define PADB   144
#define QTILE  (128*PADB)       // 18432
#define KVTILE (64*PADB)        // 9216
#define ASTAGE (4*KVTILE)       // 36864
#define ATTN_SMEM (2*QTILE + 2*ASTAGE)   // 110592

__global__ __launch_bounds__(256, 1)
void attn_mma()
{
    extern __shared__ char smem[];
    uint32_t sb = smem_u32(smem);
    int tid = threadIdx.x, wid = tid >> 5, lid = tid & 31;
    int qt = blockIdx.x, h = blockIdx.y, b = blockIdx.z;
    int q0 = qt * 128;
    int wm = wid;
    int g = lid >> 3, rr = lid & 7;
    uint32_t a_off = (uint32_t)(((g & 1) * 8 + rr) * PADB + (g >> 1) * 16);
    uint32_t b_off = (uint32_t)(((g >> 1) * 8 + rr) * PADB + (g & 1) * 16);
    int t4 = lid >> 2, t2 = lid & 3;

    size_t hb = (size_t)(b * NH + h);
    const bf16* qhB = g_qhi + hb * CTX * HS;
    const bf16* qlB = g_qlo + hb * CTX * HS;
    const bf16* khB = g_khi + hb * CTX * HS;
    const bf16* klB = g_klo + hb * CTX * HS;
    const bf16* vhB = g_vthi + hb * HS * CTX;
    const bf16* vlB = g_vtlo + hb * HS * CTX;

    // Q tile (128 x 64) hi/lo
#pragma unroll
    for (int i = 0; i < 4; i++) {
        int idx = tid + i * 256;
        int r = idx >> 3, ch = idx & 7;
        uint32_t so = (uint32_t)(r * PADB + ch * 16);
        size_t gg = (size_t)(q0 + r) * HS + ch * 8;
        cp16(sb + so, qhB + gg);
        cp16(sb + QTILE + so, qlB + gg);
    }
    CP_COMMIT();

#define LOAD_TILE(st, kb_) do {                                            \
        uint32_t bs = sb + 2 * QTILE + (st) * ASTAGE;                      \
        for (int i_ = 0; i_ < 2; i_++) {                                   \
            int idx_ = tid + i_ * 256;                                     \
            int r_ = idx_ >> 3, ch_ = idx_ & 7;                            \
            uint32_t so_ = (uint32_t)(r_ * PADB + ch_ * 16);               \
            size_t kg_ = (size_t)((kb_) + r_) * HS + ch_ * 8;              \
            size_t vg_ = (size_t)r_ * CTX + (kb_) + ch_ * 8;               \
            cp16(bs + so_, khB + kg_);                                     \
            cp16(bs + KVTILE + so_, klB + kg_);                            \
            cp16(bs + 2 * KVTILE + so_, vhB + vg_);                        \
            cp16(bs + 3 * KVTILE + so_, vlB + vg_);                        \
        } } while (0)

    LOAD_TILE(0, 0);
    CP_COMMIT();

    uint32_t qfh[4][4], qfl[4][4];
    float of[8][4];
#pragma unroll
    for (int i = 0; i < 8; i++)
#pragma unroll
        for (int j = 0; j < 4; j++) of[i][j] = 0.f;
    float m0 = -1e30f, m1 = -1e30f, l0 = 0.f, l1 = 0.f;
    bool qload = false;

    int nkt = 2 * qt + 2;
    for (int kt = 0; kt < nkt; kt++) {
        int kb = kt * 64;
        if (kt + 1 < nkt) { LOAD_TILE((kt + 1) & 1, kb + 64); CP_COMMIT(); CP_WAIT(1); }
        else { CP_WAIT(0); }
        __syncthreads();
        if (!qload) {
#pragma unroll
            for (int ks = 0; ks < 4; ks++) {
                uint32_t qo = (uint32_t)((wm * 16) * PADB + ks * 32) + a_off;
                ldm4(qfh[ks], sb + qo);
                ldm4(qfl[ks], sb + QTILE + qo);
            }
            qload = true;
        }
        if (q0 + wm * 16 + 15 >= kb) {
            uint32_t base = sb + 2 * QTILE + (kt & 1) * ASTAGE;
            float sf[8][4];
#pragma unroll
            for (int i = 0; i < 8; i++)
#pragma unroll
                for (int j = 0; j < 4; j++) sf[i][j] = 0.f;

#pragma unroll
            for (int ks = 0; ks < 4; ks++) {
                uint32_t bh[4][4], bl[4][4];
#pragma unroll
                for (int p = 0; p < 4; p++) {
                    uint32_t off = (uint32_t)((p * 16) * PADB + ks * 32) + b_off;
                    ldm4(bh[p], base + off);
                    ldm4(bl[p], base + KVTILE + off);
                }
#pragma unroll
                for (int ni = 0; ni < 8; ni++) {
                    int p = ni >> 1, o = (ni & 1) * 2;
                    mma_bf16(sf[ni], qfh[ks], &bh[p][o]);
                    mma_bf16(sf[ni], qfh[ks], &bl[p][o]);
                    mma_bf16(sf[ni], qfl[ks], &bh[p][o]);
                }
            }

            int row0 = q0 + wm * 16 + t4, row1 = row0 + 8;
            bool needm = (kb + 63 > q0 + wm * 16);
            float mx0 = -1e30f, mx1 = -1e30f;
#pragma unroll
            for (int ni = 0; ni < 8; ni++) {
                int c = kb + ni * 8 + t2 * 2;
                float s0 = sf[ni][0] * 0.125f, s1 = sf[ni][1] * 0.125f;
                float s2 = sf[ni][2] * 0.125f, s3 = sf[ni][3] * 0.125f;
                if (needm) {
                    if (c > row0)     s0 = -1e30f;
                    if (c + 1 > row0) s1 = -1e30f;
                    if (c > row1)     s2 = -1e30f;
                    if (c + 1 > row1) s3 = -1e30f;
                }
                sf[ni][0] = s0; sf[ni][1] = s1; sf[ni][2] = s2; sf[ni][3] = s3;
                mx0 = fmaxf(mx0, fmaxf(s0, s1));
                mx1 = fmaxf(mx1, fmaxf(s2, s3));
            }
            mx0 = fmaxf(mx0, __shfl_xor_sync(0xffffffffu, mx0, 1));
            mx0 = fmaxf(mx0, __shfl_xor_sync(0xffffffffu, mx0, 2));
            mx1 = fmaxf(mx1, __shfl_xor_sync(0xffffffffu, mx1, 1));
            mx1 = fmaxf(mx1, __shfl_xor_sync(0xffffffffu, mx1, 2));
            float nm0 = fmaxf(m0, mx0), nm1 = fmaxf(m1, mx1);
            float cr0 = __expf(m0 - nm0), cr1 = __expf(m1 - nm1);
            m0 = nm0; m1 = nm1;
            l0 *= cr0; l1 *= cr1;
#pragma unroll
            for (int ni = 0; ni < 8; ni++) {
                float p0 = __expf(sf[ni][0] - m0), p1 = __expf(sf[ni][1] - m0);
                float p2 = __expf(sf[ni][2] - m1), p3 = __expf(sf[ni][3] - m1);
                sf[ni][0] = p0; sf[ni][1] = p1; sf[ni][2] = p2; sf[ni][3] = p3;
                l0 += p0 + p1; l1 += p2 + p3;
                of[ni][0] *= cr0; of[ni][1] *= cr0; of[ni][2] *= cr1; of[ni][3] *= cr1;
            }

#pragma unroll
            for (int ks2 = 0; ks2 < 4; ks2++) {
                int n0b = 2 * ks2, n1b = n0b + 1;
                uint32_t pah[4], pal[4];
                pah[0] = pack2bf(sf[n0b][0], sf[n0b][1]);
                pah[1] = pack2bf(sf[n0b][2], sf[n0b][3]);
                pah[2] = pack2bf(sf[n1b][0], sf[n1b][1]);
                pah[3] = pack2bf(sf[n1b][2], sf[n1b][3]);
                pal[0] = packlo2(sf[n0b][0], sf[n0b][1]);
                pal[1] = packlo2(sf[n0b][2], sf[n0b][3]);
                pal[2] = packlo2(sf[n1b][0], sf[n1b][1]);
                pal[3] = packlo2(sf[n1b][2], sf[n1b][3]);
                uint32_t vh[4][4], vl[4][4];
#pragma unroll
                for (int p = 0; p < 4; p++) {
                    uint32_t off = (uint32_t)((p * 16) * PADB + ks2 * 32) + b_off;
                    ldm4(vh[p], base + 2 * KVTILE + off);
                    ldm4(vl[p], base + 3 * KVTILE + off);
                }
#pragma unroll
                for (int ni = 0; ni < 8; ni++) {
                    int p = ni >> 1, o = (ni & 1) * 2;
                    mma_bf16(of[ni], pah, &vh[p][o]);
                    mma_bf16(of[ni], pah, &vl[p][o]);
                    mma_bf16(of[ni], pal, &vh[p][o]);
                }
            }
        }
        __syncthreads();
    }
#undef LOAD_TILE

    l0 += __shfl_xor_sync(0xffffffffu, l0, 1);
    l0 += __shfl_xor_sync(0xffffffffu, l0, 2);
    l1 += __shfl_xor_sync(0xffffffffu, l1, 1);
    l1 += __shfl_xor_sync(0xffffffffu, l1, 2);
    float inv0 = 1.f / l0, inv1 = 1.f / l1;

    int row0 = q0 + wm * 16 + t4;
#pragma unroll
    for (int ni = 0; ni < 8; ni++) {
        int col = h * HS + ni * 8 + t2 * 2;
        float v0 = of[ni][0] * inv0, v1 = of[ni][1] * inv0;
        float v2 = of[ni][2] * inv1, v3 = of[ni][3] * inv1;
        size_t o0 = ((size_t)(b * CTX) + row0) * DM + col;
        size_t o1 = o0 + (size_t)8 * DM;
        *(uint32_t*)(g_ahi + o0) = pack2bf(v0, v1);
        *(uint32_t*)(g_alo + o0) = packlo2(v0, v1);
        *(uint32_t*)(g_ahi + o1) = pack2bf(v2, v3);
        *(uint32_t*)(g_alo + o1) = packlo2(v2, v3);
    }
}

// ================= launch =================
extern "C" void kernel_launch(void* const* d_in, const int* in_sizes, int n_in,
                              void* d_out, int out_size)
{
    const float* x  = (const float*)d_in[0];
    const float* Wq = (const float*)d_in[1];
    const float* Wk = (const float*)d_in[2];
    const float* Wv = (const float*)d_in[3];
    const float* W1 = (const float*)d_in[4];
    const float* b1 = (const float*)d_in[5];
    const float* W2 = (const float*)d_in[6];
    const float* b2 = (const float*)d_in[7];
    float* out = (float*)d_out;

    bf16 *qhi, *qlo, *khi, *klo, *vthi, *vtlo;
    bf16 *xhi, *xlo, *bqhi, *bqlo, *ahi, *alo, *w1hi, *w1lo, *hhi, *hlo, *w2hi, *w2lo;
    cudaGetSymbolAddress((void**)&qhi, g_qhi);
    cudaGetSymbolAddress((void**)&qlo, g_qlo);
    cudaGetSymbolAddress((void**)&khi, g_khi);
    cudaGetSymbolAddress((void**)&klo, g_klo);
    cudaGetSymbolAddress((void**)&vthi, g_vthi);
    cudaGetSymbolAddress((void**)&vtlo, g_vtlo);
    cudaGetSymbolAddress((void**)&xhi, g_xhi);
    cudaGetSymbolAddress((void**)&xlo, g_xlo);
    cudaGetSymbolAddress((void**)&bqhi, g_bqhi);
    cudaGetSymbolAddress((void**)&bqlo, g_bqlo);
    cudaGetSymbolAddress((void**)&ahi, g_ahi);
    cudaGetSymbolAddress((void**)&alo, g_alo);
    cudaGetSymbolAddress((void**)&w1hi, g_w1hi);
    cudaGetSymbolAddress((void**)&w1lo, g_w1lo);
    cudaGetSymbolAddress((void**)&hhi, g_hhi);
    cudaGetSymbolAddress((void**)&hlo, g_hlo);
    cudaGetSymbolAddress((void**)&w2hi, g_w2hi);
    cudaGetSymbolAddress((void**)&w2lo, g_w2lo);

    cudaFuncSetAttribute(gemm_split<0>, cudaFuncAttributeMaxDynamicSharedMemorySize, GEMM_SMEM);
    cudaFuncSetAttribute(gemm_split<1>, cudaFuncAttributeMaxDynamicSharedMemorySize, GEMM_SMEM);
    cudaFuncSetAttribute(gemm_split<2>, cudaFuncAttributeMaxDynamicSharedMemorySize, GEMM_SMEM);
    cudaFuncSetAttribute(attn_mma, cudaFuncAttributeMaxDynamicSharedMemorySize, ATTN_SMEM);

    // input conversions
    split_x_kernel<<<(size_t)MTOT * NEMB / 1024, 256>>>(x, xhi, xlo);
    qkv_transpose_split<<<dim3(NEMB / 32, HS / 32, 48), dim3(32, 8)>>>(Wq, Wk, Wv, bqhi, bqlo);
    transpose_split<<<dim3(FF / 32, DM / 32), dim3(32, 8)>>>(W1, w1hi, w1lo, DM, FF);
    transpose_split<<<dim3(DM / 32, FF / 32), dim3(32, 8)>>>(W2, w2hi, w2lo, FF, DM);

    // QKV: [8192,1024] @ [1024,3072] -> split bf16 q/k [B,H,T,D], vt [B,H,D,T]
    gemm_split<0><<<dim3(3 * DM / 128, MTOT / 128), 256, GEMM_SMEM>>>(
        xhi, xlo, bqhi, bqlo, nullptr, nullptr, qhi, qlo, khi, klo, vthi, vtlo, 3 * DM, NEMB);

    // attention -> att hi/lo
    attn_mma<<<dim3(CTX / 128, NH, BATCH), 256, ATTN_SMEM>>>();

    // FFN1: [8192,1024] @ [1024,4096] + b1 -> h hi/lo
    gemm_split<1><<<dim3(FF / 128, MTOT / 128), 256, GEMM_SMEM>>>(
        ahi, alo, w1hi, w1lo, b1, nullptr, hhi, hlo, nullptr, nullptr, nullptr, nullptr, FF, DM);

    // FFN2: [8192,4096] @ [4096,1024] + b2, relu -> out
    gemm_split<2><<<dim3(DM / 128, MTOT / 128), 256, GEMM_SMEM>>>(
        hhi, hlo, w2hi, w2lo, b2, out, nullptr, nullptr, nullptr, nullptr, nullptr, nullptr, DM, FF);
}